// round 1
// baseline (speedup 1.0000x reference)
#include <cuda_runtime.h>

#define NNODES 100000
#define D      128
#define R      4
#define EDGES  500000
#define CAP    64
#define NROWS  (R * NNODES)   // 400000

// ---------------- static scratch (no allocations allowed) ----------------
__device__ int   g_cnt[NROWS];                       // 1.6 MB
__device__ int   g_bucket[(long long)NROWS * CAP];   // 102.4 MB
__device__ float g_neigh[(long long)NROWS * D];      // 204.8 MB  (neigh per relation, already divided)
__device__ float g_wcomb[D * D];                     // sum_r Wself_r
__device__ float g_bcomb[D];                         // sum_r b_r

// ---------------- K0: zero counters ----------------
__global__ void k_zero_cnt() {
    int i = blockIdx.x * blockDim.x + threadIdx.x;
    if (i < NROWS) g_cnt[i] = 0;
}

// ---------------- K1: build inverted-index buckets ----------------
__global__ void k_bucket(const int* __restrict__ src, const int* __restrict__ dst) {
    int i = blockIdx.x * blockDim.x + threadIdx.x;
    if (i >= R * EDGES) return;
    int r = i / EDGES;
    int d = dst[i];
    int s = src[i];
    int row = r * NNODES + d;
    int p = atomicAdd(&g_cnt[row], 1);
    if (p < CAP) g_bucket[(long long)row * CAP + p] = s;
}

// ---------------- K2: combine weights (fold mean over relations) ----------------
__global__ void k_wcomb(const float* __restrict__ Wself, const float* __restrict__ b) {
    int i = blockIdx.x * blockDim.x + threadIdx.x;
    if (i < D * D) {
        float s = 0.f;
        #pragma unroll
        for (int r = 0; r < R; r++) s += Wself[r * D * D + i];
        g_wcomb[i] = s;
    }
    if (i < D) {
        float s = 0.f;
        #pragma unroll
        for (int r = 0; r < R; r++) s += b[r * D + i];
        g_bcomb[i] = s;
    }
}

// ---------------- K3: aggregate (mean of neighbor features), warp per (r,node) ----------------
__global__ void k_agg(const float* __restrict__ x) {
    int gwarp = (blockIdx.x * blockDim.x + threadIdx.x) >> 5;
    int lane  = threadIdx.x & 31;
    if (gwarp >= NROWS) return;

    int c = g_cnt[gwarp];
    int m = min(c, CAP);
    const int* bk = &g_bucket[(long long)gwarp * CAP];

    float4 acc = make_float4(0.f, 0.f, 0.f, 0.f);
    for (int base = 0; base < m; base += 32) {
        int nb = min(m - base, 32);
        int sv = (lane < nb) ? bk[base + lane] : 0;
        #pragma unroll 4
        for (int j = 0; j < nb; j++) {
            int s = __shfl_sync(0xffffffffu, sv, j);
            float4 v = *(const float4*)(x + (long long)s * D + lane * 4);
            acc.x += v.x; acc.y += v.y; acc.z += v.z; acc.w += v.w;
        }
    }
    float inv = 1.0f / (float)max(c, 1);
    acc.x *= inv; acc.y *= inv; acc.z *= inv; acc.w *= inv;
    *(float4*)(g_neigh + (long long)gwarp * D + lane * 4) = acc;
}

// ---------------- K4: fused GEMM  out = (x@Wcomb + sum_r neigh_r@Wneigh_r + bcomb) / R ----------------
// Logical A = [x | neigh_0 | neigh_1 | neigh_2 | neigh_3]  (N x 640)
// Logical B = [Wcomb ; Wneigh_0 ; ... ; Wneigh_3]          (640 x 128)
#define BM 128
#define BK 16
#define KTOT ((R + 1) * D)   // 640

__global__ __launch_bounds__(256) void k_gemm(const float* __restrict__ x,
                                              const float* __restrict__ Wneigh,
                                              float* __restrict__ out) {
    __shared__ float As[BK][BM];   // transposed: [k][row]
    __shared__ float Bs[BK][D];    // [k][col]

    int tid = threadIdx.x;
    int ty = tid >> 4;        // 0..15 -> row groups
    int tx = tid & 15;        // 0..15 -> col groups
    int rbase = blockIdx.x * BM;

    float acc[8][8];
    #pragma unroll
    for (int i = 0; i < 8; i++)
        #pragma unroll
        for (int j = 0; j < 8; j++) acc[i][j] = 0.f;

    for (int kb = 0; kb < KTOT; kb += BK) {
        int seg = kb >> 7;        // 0 -> x/Wcomb, 1..4 -> neigh_{seg-1}/Wneigh_{seg-1}
        int kl  = kb & 127;       // offset within the 128-wide segment

        // load A tile: 128 rows x 16 k  (512 float4, 2 per thread)
        #pragma unroll
        for (int l = 0; l < 2; l++) {
            int idx = tid + l * 256;
            int row = idx >> 2;            // 0..127
            int kq  = (idx & 3) * 4;       // 0,4,8,12
            int grow = min(rbase + row, NNODES - 1);
            const float* srcp = (seg == 0)
                ? (x + (long long)grow * D + kl + kq)
                : (g_neigh + ((long long)(seg - 1) * NNODES + grow) * D + kl + kq);
            float4 v = *(const float4*)srcp;
            As[kq + 0][row] = v.x;
            As[kq + 1][row] = v.y;
            As[kq + 2][row] = v.z;
            As[kq + 3][row] = v.w;
        }
        // load B tile: 16 k x 128 cols (512 float4, 2 per thread)
        #pragma unroll
        for (int l = 0; l < 2; l++) {
            int idx = tid + l * 256;
            int k   = idx >> 5;            // 0..15
            int cq  = (idx & 31) * 4;      // 0..124
            const float* srcp = (seg == 0)
                ? (g_wcomb + (kl + k) * D + cq)
                : (Wneigh + ((long long)(seg - 1) * D + kl + k) * D + cq);
            *(float4*)&Bs[k][cq] = *(const float4*)srcp;
        }
        __syncthreads();

        #pragma unroll
        for (int kk = 0; kk < BK; kk++) {
            float a[8], bb[8];
            *(float4*)(a)     = *(const float4*)&As[kk][ty * 4];
            *(float4*)(a + 4) = *(const float4*)&As[kk][64 + ty * 4];
            *(float4*)(bb)     = *(const float4*)&Bs[kk][tx * 4];
            *(float4*)(bb + 4) = *(const float4*)&Bs[kk][64 + tx * 4];
            #pragma unroll
            for (int i = 0; i < 8; i++)
                #pragma unroll
                for (int j = 0; j < 8; j++)
                    acc[i][j] = fmaf(a[i], bb[j], acc[i][j]);
        }
        __syncthreads();
    }

    // epilogue: out = (acc + bcomb) * 0.25
    const float invR = 1.0f / (float)R;
    float bias[8];
    #pragma unroll
    for (int j = 0; j < 8; j++) {
        int col = (j < 4) ? (tx * 4 + j) : (64 + tx * 4 + (j - 4));
        bias[j] = g_bcomb[col];
    }
    #pragma unroll
    for (int i = 0; i < 8; i++) {
        int row = rbase + ((i < 4) ? (ty * 4 + i) : (64 + ty * 4 + (i - 4)));
        if (row < NNODES) {
            float4 v0, v1;
            v0.x = (acc[i][0] + bias[0]) * invR;
            v0.y = (acc[i][1] + bias[1]) * invR;
            v0.z = (acc[i][2] + bias[2]) * invR;
            v0.w = (acc[i][3] + bias[3]) * invR;
            v1.x = (acc[i][4] + bias[4]) * invR;
            v1.y = (acc[i][5] + bias[5]) * invR;
            v1.z = (acc[i][6] + bias[6]) * invR;
            v1.w = (acc[i][7] + bias[7]) * invR;
            *(float4*)(out + (long long)row * D + tx * 4)      = v0;
            *(float4*)(out + (long long)row * D + 64 + tx * 4) = v1;
        }
    }
}

// ---------------- launch ----------------
extern "C" void kernel_launch(void* const* d_in, const int* in_sizes, int n_in,
                              void* d_out, int out_size) {
    const float* x      = (const float*)d_in[0];   // [N, D]
    const int*   src    = (const int*)d_in[1];     // [R, E]
    const int*   dst    = (const int*)d_in[2];     // [R, E]
    const float* Wself  = (const float*)d_in[3];   // [R, D, D]
    const float* Wneigh = (const float*)d_in[4];   // [R, D, D]
    const float* b      = (const float*)d_in[5];   // [R, D]
    float* out = (float*)d_out;                    // [N, D]

    k_zero_cnt<<<(NROWS + 255) / 256, 256>>>();
    k_bucket<<<(R * EDGES + 255) / 256, 256>>>(src, dst);
    k_wcomb<<<(D * D + 255) / 256, 256>>>(Wself, b);
    k_agg<<<(NROWS * 32 + 255) / 256, 256>>>(x);
    k_gemm<<<(NNODES + BM - 1) / BM, 256>>>(x, Wneigh, out);
}

// round 3
// speedup vs baseline: 1.5004x; 1.5004x over previous
#include <cuda_runtime.h>
#include <cuda_bf16.h>
#include <cstdint>

#define NNODES 100000
#define D      128
#define R      4
#define EDGES  500000
#define CAP    64
#define NROWS  (R * NNODES)       // 400000
#define KTOT   ((R + 1) * D)      // 640
#define KC     32                 // K-chunk
#define NCHUNK (KTOT / KC)        // 20
#define ASTRIDE 40                // padded smem stride in halves (conflict-free)

// ---------------- static scratch ----------------
__device__ int   g_cnt[NROWS];
__device__ int   g_bucket[(long long)NROWS * CAP];
__device__ float g_neigh[(long long)NROWS * D];
__device__ float g_bcomb[D];
__device__ __nv_bfloat16 g_Bh[D * KTOT];   // [n][k] K-major, hi part
__device__ __nv_bfloat16 g_Bl[D * KTOT];   // lo part

// ---------------- K0: zero counters ----------------
__global__ void k_zero_cnt() {
    int i = blockIdx.x * blockDim.x + threadIdx.x;
    if (i < NROWS) g_cnt[i] = 0;
}

// ---------------- K1: build inverted-index buckets ----------------
__global__ void k_bucket(const int* __restrict__ src, const int* __restrict__ dst) {
    int i = blockIdx.x * blockDim.x + threadIdx.x;
    if (i >= R * EDGES) return;
    int r = i / EDGES;
    int d = dst[i];
    int s = src[i];
    int row = r * NNODES + d;
    int p = atomicAdd(&g_cnt[row], 1);
    if (p < CAP) g_bucket[(long long)row * CAP + p] = s;
}

// ---------------- K2: precompute B (K-major bf16 hi/lo) + combined bias ----------------
// Logical Bfull[k][n]: k<128 -> sum_r Wself[r][k][n]; else Wneigh[seg-1][k%128][n]
// Stored transposed: g_B*[n*KTOT + k]
__global__ void k_prepB(const float* __restrict__ Wself, const float* __restrict__ Wneigh,
                        const float* __restrict__ b) {
    int i = blockIdx.x * blockDim.x + threadIdx.x;
    if (i < D * KTOT) {
        int n = i / KTOT, k = i % KTOT;
        int seg = k >> 7, kl = k & 127;
        float w;
        if (seg == 0) {
            w = 0.f;
            #pragma unroll
            for (int r = 0; r < R; r++) w += Wself[r * D * D + kl * D + n];
        } else {
            w = Wneigh[(seg - 1) * D * D + kl * D + n];
        }
        __nv_bfloat16 h = __float2bfloat16_rn(w);
        float fl = w - __bfloat162float(h);
        g_Bh[i] = h;
        g_Bl[i] = __float2bfloat16_rn(fl);
    }
    if (i < D) {
        float s = 0.f;
        #pragma unroll
        for (int r = 0; r < R; r++) s += b[r * D + i];
        g_bcomb[i] = s;
    }
}

// ---------------- K3: aggregate (mean over neighbors), warp per (r,node) ----------------
__global__ void k_agg(const float* __restrict__ x) {
    int gwarp = (blockIdx.x * blockDim.x + threadIdx.x) >> 5;
    int lane  = threadIdx.x & 31;
    if (gwarp >= NROWS) return;

    int c = g_cnt[gwarp];
    int m = min(c, CAP);
    const int* bk = &g_bucket[(long long)gwarp * CAP];

    float4 acc = make_float4(0.f, 0.f, 0.f, 0.f);
    for (int base = 0; base < m; base += 32) {
        int nb = min(m - base, 32);
        int sv = (lane < nb) ? bk[base + lane] : 0;
        #pragma unroll 4
        for (int j = 0; j < nb; j++) {
            int s = __shfl_sync(0xffffffffu, sv, j);
            float4 v = *(const float4*)(x + (long long)s * D + lane * 4);
            acc.x += v.x; acc.y += v.y; acc.z += v.z; acc.w += v.w;
        }
    }
    float inv = 1.0f / (float)max(c, 1);
    acc.x *= inv; acc.y *= inv; acc.z *= inv; acc.w *= inv;
    *(float4*)(g_neigh + (long long)gwarp * D + lane * 4) = acc;
}

// ---------------- mma.sync helper ----------------
__device__ __forceinline__ void mma16816(float* c, const uint32_t* a, const uint32_t* b) {
    asm volatile(
        "mma.sync.aligned.m16n8k16.row.col.f32.bf16.bf16.f32 "
        "{%0,%1,%2,%3}, {%4,%5,%6,%7}, {%8,%9}, {%0,%1,%2,%3};"
        : "+f"(c[0]), "+f"(c[1]), "+f"(c[2]), "+f"(c[3])
        : "r"(a[0]), "r"(a[1]), "r"(a[2]), "r"(a[3]), "r"(b[0]), "r"(b[1]));
}

// ---------------- K4: HMMA GEMM with 3x-bf16 split ----------------
// A = [x | neigh_0..3] (N x 640 fp32), B^T precomputed bf16 hi/lo (128 x 640)
// out = (A@B + bcomb) / R
// Block tile 128x128, 8 warps (2x4), warp tile 64x32 (4 m-tiles x 4 n-tiles)
__global__ __launch_bounds__(256, 2)
void k_gemm_mma(const float* __restrict__ x, float* __restrict__ out) {
    __shared__ __nv_bfloat16 sAh[128][ASTRIDE];
    __shared__ __nv_bfloat16 sAl[128][ASTRIDE];
    __shared__ __nv_bfloat16 sBh[128][ASTRIDE];
    __shared__ __nv_bfloat16 sBl[128][ASTRIDE];

    const int tid  = threadIdx.x;
    const int wid  = tid >> 5;
    const int lane = tid & 31;
    const int wm = (wid >> 2) * 64;   // warp row base
    const int wn = (wid & 3) * 32;    // warp col base
    const int gid = lane >> 2;
    const int tig = lane & 3;
    const int rbase = blockIdx.x * 128;

    float acc[4][4][4];
    #pragma unroll
    for (int i = 0; i < 4; i++)
        #pragma unroll
        for (int j = 0; j < 4; j++)
            #pragma unroll
            for (int q = 0; q < 4; q++) acc[i][j][q] = 0.f;

    for (int c = 0; c < NCHUNK; c++) {
        const int kc  = c * KC;
        const int seg = kc >> 7;
        const int kl  = kc & 127;

        __syncthreads();
        // ---- stage A: 128 rows x 32 k fp32 -> bf16 hi/lo (1024 float4 slots) ----
        #pragma unroll
        for (int l = 0; l < 4; l++) {
            int idx = l * 256 + tid;
            int row = idx >> 3;            // 0..127
            int kq  = (idx & 7) * 4;       // 0..28
            int grow = min(rbase + row, NNODES - 1);
            const float* sp = (seg == 0)
                ? (x + (long long)grow * D + kl + kq)
                : (g_neigh + ((long long)(seg - 1) * NNODES + grow) * D + kl + kq);
            float4 f = *(const float4*)sp;
            __nv_bfloat162 h01 = __floats2bfloat162_rn(f.x, f.y);
            __nv_bfloat162 h23 = __floats2bfloat162_rn(f.z, f.w);
            __nv_bfloat162 l01 = __floats2bfloat162_rn(f.x - __bfloat162float(h01.x),
                                                       f.y - __bfloat162float(h01.y));
            __nv_bfloat162 l23 = __floats2bfloat162_rn(f.z - __bfloat162float(h23.x),
                                                       f.w - __bfloat162float(h23.y));
            uint2 uh, ul;
            uh.x = *(uint32_t*)&h01; uh.y = *(uint32_t*)&h23;
            ul.x = *(uint32_t*)&l01; ul.y = *(uint32_t*)&l23;
            *(uint2*)&sAh[row][kq] = uh;
            *(uint2*)&sAl[row][kq] = ul;
        }
        // ---- stage B: 2 mats x 128 n x 32 k halves (1024 slots of 8 halves) ----
        #pragma unroll
        for (int l = 0; l < 4; l++) {
            int idx = l * 256 + tid;
            int mat = idx >> 9;            // 0: hi, 1: lo
            int rem = idx & 511;
            int n   = rem >> 2;            // 0..127
            int kq8 = (rem & 3) * 8;       // 0,8,16,24
            const __nv_bfloat16* sp = (mat ? g_Bl : g_Bh) + n * KTOT + kc + kq8;
            float4 v = *(const float4*)sp;
            if (mat) *(float4*)&sBl[n][kq8] = v;
            else     *(float4*)&sBh[n][kq8] = v;
        }
        __syncthreads();

        // ---- compute: 2 k16 steps ----
        #pragma unroll
        for (int s = 0; s < 2; s++) {
            const int kb = s * 16;
            uint32_t a[4][4], b[4][2];

            // Ah frags
            #pragma unroll
            for (int i = 0; i < 4; i++) {
                int r0 = wm + i * 16 + gid;
                a[i][0] = *(const uint32_t*)&sAh[r0][kb + tig * 2];
                a[i][1] = *(const uint32_t*)&sAh[r0 + 8][kb + tig * 2];
                a[i][2] = *(const uint32_t*)&sAh[r0][kb + 8 + tig * 2];
                a[i][3] = *(const uint32_t*)&sAh[r0 + 8][kb + 8 + tig * 2];
            }
            // Bh frags
            #pragma unroll
            for (int j = 0; j < 4; j++) {
                int n0 = wn + j * 8 + gid;
                b[j][0] = *(const uint32_t*)&sBh[n0][kb + tig * 2];
                b[j][1] = *(const uint32_t*)&sBh[n0][kb + 8 + tig * 2];
            }
            #pragma unroll
            for (int i = 0; i < 4; i++)
                #pragma unroll
                for (int j = 0; j < 4; j++) mma16816(acc[i][j], a[i], b[j]);

            // Bl frags (overwrite b)
            #pragma unroll
            for (int j = 0; j < 4; j++) {
                int n0 = wn + j * 8 + gid;
                b[j][0] = *(const uint32_t*)&sBl[n0][kb + tig * 2];
                b[j][1] = *(const uint32_t*)&sBl[n0][kb + 8 + tig * 2];
            }
            #pragma unroll
            for (int i = 0; i < 4; i++)
                #pragma unroll
                for (int j = 0; j < 4; j++) mma16816(acc[i][j], a[i], b[j]);

            // Al frags (overwrite a), reload Bh
            #pragma unroll
            for (int i = 0; i < 4; i++) {
                int r0 = wm + i * 16 + gid;
                a[i][0] = *(const uint32_t*)&sAl[r0][kb + tig * 2];
                a[i][1] = *(const uint32_t*)&sAl[r0 + 8][kb + tig * 2];
                a[i][2] = *(const uint32_t*)&sAl[r0][kb + 8 + tig * 2];
                a[i][3] = *(const uint32_t*)&sAl[r0 + 8][kb + 8 + tig * 2];
            }
            #pragma unroll
            for (int j = 0; j < 4; j++) {
                int n0 = wn + j * 8 + gid;
                b[j][0] = *(const uint32_t*)&sBh[n0][kb + tig * 2];
                b[j][1] = *(const uint32_t*)&sBh[n0][kb + 8 + tig * 2];
            }
            #pragma unroll
            for (int i = 0; i < 4; i++)
                #pragma unroll
                for (int j = 0; j < 4; j++) mma16816(acc[i][j], a[i], b[j]);
        }
    }

    // ---- epilogue ----
    const float invR = 1.0f / (float)R;
    #pragma unroll
    for (int j = 0; j < 4; j++) {
        int col = wn + j * 8 + tig * 2;
        float b0 = g_bcomb[col], b1 = g_bcomb[col + 1];
        #pragma unroll
        for (int i = 0; i < 4; i++) {
            int row0 = rbase + wm + i * 16 + gid;
            if (row0 < NNODES) {
                float2 v;
                v.x = (acc[i][j][0] + b0) * invR;
                v.y = (acc[i][j][1] + b1) * invR;
                *(float2*)(out + (long long)row0 * D + col) = v;
            }
            int row1 = row0 + 8;
            if (row1 < NNODES) {
                float2 v;
                v.x = (acc[i][j][2] + b0) * invR;
                v.y = (acc[i][j][3] + b1) * invR;
                *(float2*)(out + (long long)row1 * D + col) = v;
            }
        }
    }
}

// ---------------- launch ----------------
extern "C" void kernel_launch(void* const* d_in, const int* in_sizes, int n_in,
                              void* d_out, int out_size) {
    const float* x      = (const float*)d_in[0];
    const int*   src    = (const int*)d_in[1];
    const int*   dst    = (const int*)d_in[2];
    const float* Wself  = (const float*)d_in[3];
    const float* Wneigh = (const float*)d_in[4];
    const float* b      = (const float*)d_in[5];
    float* out = (float*)d_out;

    k_zero_cnt<<<(NROWS + 255) / 256, 256>>>();
    k_bucket<<<(R * EDGES + 255) / 256, 256>>>(src, dst);
    k_prepB<<<(D * KTOT + 255) / 256, 256>>>(Wself, Wneigh, b);
    k_agg<<<(NROWS * 32 + 255) / 256, 256>>>(x);
    k_gemm_mma<<<(NNODES + 127) / 128, 256>>>(x, out);
}

// round 4
// speedup vs baseline: 1.7071x; 1.1377x over previous
#include <cuda_runtime.h>
#include <cuda_bf16.h>
#include <cstdint>

#define NNODES 100000
#define D      128
#define R      4
#define EDGES  500000
#define CAP    32
#define NROWS  (R * NNODES)       // 400000
#define KTOT   ((R + 1) * D)      // 640
#define NKSTEP (KTOT / 16)        // 40
#define ASTRIDE 136               // padded A stride in halves

// ---------------- static scratch ----------------
__device__ int   g_cnt[NROWS];
__device__ int   g_bucket[(long long)NROWS * CAP];   // 51.2 MB
__device__ float g_bcomb[D];
// B pre-packed in mma-fragment order:
// index [kstep][n][tig] -> uint2 { halves(k0+2t, k0+2t+1), halves(k0+8+2t, k0+8+2t+1) }
__device__ uint2 g_Bfh[NKSTEP * 128 * 4];  // 160 KB hi
__device__ uint2 g_Bfl[NKSTEP * 128 * 4];  // 160 KB lo

// ---------------- K0: zero counters ----------------
__global__ void k_zero_cnt() {
    int i = blockIdx.x * blockDim.x + threadIdx.x;
    if (i < NROWS) g_cnt[i] = 0;
}

// ---------------- K1: build inverted-index buckets ----------------
__global__ void k_bucket(const int* __restrict__ src, const int* __restrict__ dst) {
    int i = blockIdx.x * blockDim.x + threadIdx.x;
    if (i >= R * EDGES) return;
    int r = i / EDGES;
    int d = dst[i];
    int s = src[i];
    int row = r * NNODES + d;
    int p = atomicAdd(&g_cnt[row], 1);
    if (p < CAP) g_bucket[(long long)row * CAP + p] = s;
}

// ---------------- K2: pack B in fragment order + combined bias ----------------
// Logical Bfull[k][n]: k<128 -> sum_r Wself[r][k][n]; else Wneigh[seg-1][k%128][n]
__device__ __forceinline__ float bval(const float* Ws, const float* Wn, int k, int n) {
    int seg = k >> 7, kl = k & 127;
    if (seg == 0) {
        float s = 0.f;
        #pragma unroll
        for (int r = 0; r < R; r++) s += Ws[r * D * D + kl * D + n];
        return s;
    }
    return Wn[(seg - 1) * D * D + kl * D + n];
}

__global__ void k_prepB(const float* __restrict__ Wself, const float* __restrict__ Wneigh,
                        const float* __restrict__ b) {
    int i = blockIdx.x * blockDim.x + threadIdx.x;   // (kstep, n, tig)
    if (i < NKSTEP * 128 * 4) {
        int tig = i & 3;
        int n   = (i >> 2) & 127;
        int ks  = i >> 9;
        int k0  = ks * 16 + tig * 2;
        float w0 = bval(Wself, Wneigh, k0, n);
        float w1 = bval(Wself, Wneigh, k0 + 1, n);
        float w2 = bval(Wself, Wneigh, k0 + 8, n);
        float w3 = bval(Wself, Wneigh, k0 + 9, n);
        __nv_bfloat162 h01, h23, l01, l23;
        h01 = __floats2bfloat162_rn(w0, w1);
        h23 = __floats2bfloat162_rn(w2, w3);
        l01 = __floats2bfloat162_rn(w0 - __bfloat162float(h01.x), w1 - __bfloat162float(h01.y));
        l23 = __floats2bfloat162_rn(w2 - __bfloat162float(h23.x), w3 - __bfloat162float(h23.y));
        uint2 uh, ul;
        uh.x = *(uint32_t*)&h01; uh.y = *(uint32_t*)&h23;
        ul.x = *(uint32_t*)&l01; ul.y = *(uint32_t*)&l23;
        g_Bfh[i] = uh;
        g_Bfl[i] = ul;
    }
    if (i < D) {
        float s = 0.f;
        #pragma unroll
        for (int r = 0; r < R; r++) s += b[r * D + i];
        g_bcomb[i] = s;
    }
}

// ---------------- mma helpers ----------------
__device__ __forceinline__ void mma16816(float* c, const uint32_t* a, const uint32_t* b) {
    asm volatile(
        "mma.sync.aligned.m16n8k16.row.col.f32.bf16.bf16.f32 "
        "{%0,%1,%2,%3}, {%4,%5,%6,%7}, {%8,%9}, {%0,%1,%2,%3};"
        : "+f"(c[0]), "+f"(c[1]), "+f"(c[2]), "+f"(c[3])
        : "r"(a[0]), "r"(a[1]), "r"(a[2]), "r"(a[3]), "r"(b[0]), "r"(b[1]));
}
__device__ __forceinline__ void ldmat4(uint32_t* r, uint32_t addr) {
    asm volatile("ldmatrix.sync.aligned.m8n8.x4.shared.b16 {%0,%1,%2,%3}, [%4];"
        : "=r"(r[0]), "=r"(r[1]), "=r"(r[2]), "=r"(r[3]) : "r"(addr));
}
__device__ __forceinline__ uint32_t smem_u32(const void* p) {
    uint32_t a;
    asm("{ .reg .u64 t; cvta.to.shared.u64 t, %1; cvt.u32.u64 %0, t; }" : "=r"(a) : "l"(p));
    return a;
}

// ---------------- K3: fused aggregate + GEMM ----------------
// out = ( x@sumWself + sum_r mean_neigh_r@Wneigh_r + bcomb ) / R
// Block tile 128x128 out; K processed segment-wise (5 segs of 128).
// A buffer in SMEM holds one full segment (128x128) as bf16 hi/lo.
__global__ __launch_bounds__(256, 2)
void k_fused(const float* __restrict__ x, float* __restrict__ out) {
    extern __shared__ __nv_bfloat16 dsm[];
    __nv_bfloat16* sAh = dsm;                      // [128][ASTRIDE]
    __nv_bfloat16* sAl = dsm + 128 * ASTRIDE;      // [128][ASTRIDE]

    const int tid  = threadIdx.x;
    const int wid  = tid >> 5;
    const int lane = tid & 31;
    const int wm = (wid >> 2) * 64;   // warp row base
    const int wn = (wid & 3) * 32;    // warp col base
    const int gid = lane >> 2;
    const int tig = lane & 3;
    const int rbase = blockIdx.x * 128;

    // ldmatrix per-lane addressing
    const int lrow = ((lane >> 3) & 1) * 8 + (lane & 7);
    const int lcol = (lane >> 4) * 8;
    const uint32_t aAh = smem_u32(sAh);
    const uint32_t aAl = smem_u32(sAl);

    float acc[4][4][4];
    #pragma unroll
    for (int i = 0; i < 4; i++)
        #pragma unroll
        for (int j = 0; j < 4; j++)
            #pragma unroll
            for (int q = 0; q < 4; q++) acc[i][j][q] = 0.f;

    for (int seg = 0; seg < R + 1; seg++) {
        __syncthreads();   // previous compute done with A buffer

        if (seg == 0) {
            // ---- stage x tile: 128 rows x 128 cols ----
            #pragma unroll
            for (int l = 0; l < 16; l++) {
                int idx = l * 256 + tid;           // 0..4095
                int row = idx >> 5;                // 0..127
                int q   = (idx & 31) * 4;          // col
                int grow = min(rbase + row, NNODES - 1);
                float4 f = *(const float4*)(x + (long long)grow * D + q);
                __nv_bfloat162 h01 = __floats2bfloat162_rn(f.x, f.y);
                __nv_bfloat162 h23 = __floats2bfloat162_rn(f.z, f.w);
                __nv_bfloat162 l01 = __floats2bfloat162_rn(f.x - __bfloat162float(h01.x),
                                                           f.y - __bfloat162float(h01.y));
                __nv_bfloat162 l23 = __floats2bfloat162_rn(f.z - __bfloat162float(h23.x),
                                                           f.w - __bfloat162float(h23.y));
                uint2 uh, ul;
                uh.x = *(uint32_t*)&h01; uh.y = *(uint32_t*)&h23;
                ul.x = *(uint32_t*)&l01; ul.y = *(uint32_t*)&l23;
                *(uint2*)&sAh[row * ASTRIDE + q] = uh;
                *(uint2*)&sAl[row * ASTRIDE + q] = ul;
            }
        } else {
            // ---- aggregate 16 rows per warp: mean over bucket neighbors ----
            const int rel = seg - 1;
            const long long cbase = (long long)rel * NNODES;
            int nodeL = min(rbase + wid * 16 + (lane & 15), NNODES - 1);
            int cAll = g_cnt[cbase + nodeL];

            int c0 = __shfl_sync(0xffffffffu, cAll, 0);
            int m0 = min(c0, CAP);
            int node0 = min(rbase + wid * 16, NNODES - 1);
            int sv = (lane < m0) ? g_bucket[(cbase + node0) * CAP + lane] : 0;

            #pragma unroll 1
            for (int i = 0; i < 16; i++) {
                int c = __shfl_sync(0xffffffffu, cAll, i);
                int m = min(c, CAP);
                int svc = sv;
                if (i < 15) {
                    int cn = __shfl_sync(0xffffffffu, cAll, i + 1);
                    int mn = min(cn, CAP);
                    int noden = min(rbase + wid * 16 + i + 1, NNODES - 1);
                    sv = (lane < mn) ? g_bucket[(cbase + noden) * CAP + lane] : 0;
                }
                float4 a4 = make_float4(0.f, 0.f, 0.f, 0.f);
                for (int j = 0; j < m; j++) {
                    int s = __shfl_sync(0xffffffffu, svc, j);
                    float4 v = *(const float4*)(x + (long long)s * D + lane * 4);
                    a4.x += v.x; a4.y += v.y; a4.z += v.z; a4.w += v.w;
                }
                float inv = 1.0f / (float)max(c, 1);
                a4.x *= inv; a4.y *= inv; a4.z *= inv; a4.w *= inv;
                __nv_bfloat162 h01 = __floats2bfloat162_rn(a4.x, a4.y);
                __nv_bfloat162 h23 = __floats2bfloat162_rn(a4.z, a4.w);
                __nv_bfloat162 l01 = __floats2bfloat162_rn(a4.x - __bfloat162float(h01.x),
                                                           a4.y - __bfloat162float(h01.y));
                __nv_bfloat162 l23 = __floats2bfloat162_rn(a4.z - __bfloat162float(h23.x),
                                                           a4.w - __bfloat162float(h23.y));
                uint2 uh, ul;
                uh.x = *(uint32_t*)&h01; uh.y = *(uint32_t*)&h23;
                ul.x = *(uint32_t*)&l01; ul.y = *(uint32_t*)&l23;
                int row = wid * 16 + i;
                *(uint2*)&sAh[row * ASTRIDE + lane * 4] = uh;
                *(uint2*)&sAl[row * ASTRIDE + lane * 4] = ul;
            }
        }
        __syncthreads();

        // ---- compute: 8 k16 steps over this segment ----
        #pragma unroll 1
        for (int s = 0; s < 8; s++) {
            const int kb = s * 16;
            const int kstep = seg * 8 + s;

            // B fragments (pre-packed, coalesced LDG.64, L1/L2 resident)
            uint2 bh[4], bl[4];
            #pragma unroll
            for (int j = 0; j < 4; j++) {
                int idx = (kstep << 9) + ((wn + j * 8 + gid) << 2) + tig;
                bh[j] = g_Bfh[idx];
                bl[j] = g_Bfl[idx];
            }
            // A hi fragments via ldmatrix
            uint32_t ah[4][4];
            #pragma unroll
            for (int i = 0; i < 4; i++)
                ldmat4(ah[i], aAh + (uint32_t)(((wm + i * 16 + lrow) * ASTRIDE + kb + lcol) * 2));

            #pragma unroll
            for (int i = 0; i < 4; i++)
                #pragma unroll
                for (int j = 0; j < 4; j++) mma16816(acc[i][j], ah[i], (const uint32_t*)&bh[j]);
            #pragma unroll
            for (int i = 0; i < 4; i++)
                #pragma unroll
                for (int j = 0; j < 4; j++) mma16816(acc[i][j], ah[i], (const uint32_t*)&bl[j]);

            // A lo fragments
            uint32_t al[4][4];
            #pragma unroll
            for (int i = 0; i < 4; i++)
                ldmat4(al[i], aAl + (uint32_t)(((wm + i * 16 + lrow) * ASTRIDE + kb + lcol) * 2));
            #pragma unroll
            for (int i = 0; i < 4; i++)
                #pragma unroll
                for (int j = 0; j < 4; j++) mma16816(acc[i][j], al[i], (const uint32_t*)&bh[j]);
        }
    }

    // ---- epilogue ----
    const float invR = 1.0f / (float)R;
    #pragma unroll
    for (int j = 0; j < 4; j++) {
        int col = wn + j * 8 + tig * 2;
        float b0 = g_bcomb[col], b1 = g_bcomb[col + 1];
        #pragma unroll
        for (int i = 0; i < 4; i++) {
            int row0 = rbase + wm + i * 16 + gid;
            if (row0 < NNODES) {
                float2 v;
                v.x = (acc[i][j][0] + b0) * invR;
                v.y = (acc[i][j][1] + b1) * invR;
                *(float2*)(out + (long long)row0 * D + col) = v;
            }
            int row1 = row0 + 8;
            if (row1 < NNODES) {
                float2 v;
                v.x = (acc[i][j][2] + b0) * invR;
                v.y = (acc[i][j][3] + b1) * invR;
                *(float2*)(out + (long long)row1 * D + col) = v;
            }
        }
    }
}

// ---------------- launch ----------------
#define SMEM_FUSED (2 * 128 * ASTRIDE * 2)   // 69,632 bytes

extern "C" void kernel_launch(void* const* d_in, const int* in_sizes, int n_in,
                              void* d_out, int out_size) {
    const float* x      = (const float*)d_in[0];
    const int*   src    = (const int*)d_in[1];
    const int*   dst    = (const int*)d_in[2];
    const float* Wself  = (const float*)d_in[3];
    const float* Wneigh = (const float*)d_in[4];
    const float* b      = (const float*)d_in[5];
    float* out = (float*)d_out;

    cudaFuncSetAttribute(k_fused, cudaFuncAttributeMaxDynamicSharedMemorySize, SMEM_FUSED);

    k_zero_cnt<<<(NROWS + 255) / 256, 256>>>();
    k_bucket<<<(R * EDGES + 255) / 256, 256>>>(src, dst);
    k_prepB<<<(NKSTEP * 128 * 4 + 255) / 256, 256>>>(Wself, Wneigh, b);
    k_fused<<<(NNODES + 127) / 128, 256, SMEM_FUSED>>>(x, out);
}